// round 1
// baseline (speedup 1.0000x reference)
#include <cuda_runtime.h>
#include <math.h>

#define N_NODES 4096
#define NUM_REL 200
#define D 32
#define E_EDGES 16384
#define B_ROWS 2048
#define FULL 0xffffffffu

// ---------------- scratch (no allocation allowed) ----------------
__device__ float g_h0[E_EDGES * D];
__device__ int g_src_cnt[N_NODES], g_dst_cnt[N_NODES];
__device__ int g_src_off[N_NODES], g_dst_off[N_NODES];
__device__ int g_src_cur[N_NODES], g_dst_cur[N_NODES];
__device__ int g_src_list[E_EDGES], g_dst_list[E_EDGES];

// ---------------- kernel A: h0 gather + zero counts ----------------
__global__ void k_init(const int* __restrict__ edge_type,
                       const float* __restrict__ rel_emb,
                       float* __restrict__ out) {
    int idx = blockIdx.x * blockDim.x + threadIdx.x;
    if (idx < E_EDGES * D) {
        int e = idx >> 5, d = idx & 31;
        float val = __ldg(&rel_emb[edge_type[e] * D + d]);
        g_h0[idx] = val;
        out[idx]  = val;
    }
    if (idx < N_NODES) { g_src_cnt[idx] = 0; g_dst_cnt[idx] = 0; }
}

// ---------------- kernel B: degree counts ----------------
__global__ void k_count(const int* __restrict__ edge_src,
                        const int* __restrict__ edge_dst) {
    int e = blockIdx.x * blockDim.x + threadIdx.x;
    if (e < E_EDGES) {
        atomicAdd(&g_src_cnt[edge_src[e]], 1);
        atomicAdd(&g_dst_cnt[edge_dst[e]], 1);
    }
}

// ---------------- kernel C: exclusive scan (1 block, 1024 threads) ----------------
__global__ void k_scan() {
    __shared__ int warpsums[32];
    int tid = threadIdx.x;          // 1024 threads, 4 elems each -> 4096
    int lane = tid & 31, w = tid >> 5;
    for (int which = 0; which < 2; which++) {
        const int* cnt = which ? g_dst_cnt : g_src_cnt;
        int* off = which ? g_dst_off : g_src_off;
        int* cur = which ? g_dst_cur : g_src_cur;
        int base = tid * 4;
        int c0 = cnt[base], c1 = cnt[base + 1], c2 = cnt[base + 2], c3 = cnt[base + 3];
        int s = c0 + c1 + c2 + c3;
        int sc = s;
        #pragma unroll
        for (int o = 1; o < 32; o <<= 1) {
            int n = __shfl_up_sync(FULL, sc, o);
            if (lane >= o) sc += n;
        }
        if (lane == 31) warpsums[w] = sc;
        __syncthreads();
        if (w == 0) {
            int ws = warpsums[lane];
            #pragma unroll
            for (int o = 1; o < 32; o <<= 1) {
                int n = __shfl_up_sync(FULL, ws, o);
                if (lane >= o) ws += n;
            }
            warpsums[lane] = ws;
        }
        __syncthreads();
        int excl = sc - s + (w > 0 ? warpsums[w - 1] : 0);
        off[base]     = excl;                 cur[base]     = excl;
        off[base + 1] = excl + c0;            cur[base + 1] = excl + c0;
        off[base + 2] = excl + c0 + c1;       cur[base + 2] = excl + c0 + c1;
        off[base + 3] = excl + c0 + c1 + c2;  cur[base + 3] = excl + c0 + c1 + c2;
        __syncthreads();
    }
}

// ---------------- kernel D: fill CSR lists ----------------
__global__ void k_fill(const int* __restrict__ edge_src,
                       const int* __restrict__ edge_dst) {
    int e = blockIdx.x * blockDim.x + threadIdx.x;
    if (e < E_EDGES) {
        int p = atomicAdd(&g_src_cur[edge_src[e]], 1);
        g_src_list[p] = e;
        int q = atomicAdd(&g_dst_cur[edge_dst[e]], 1);
        g_dst_list[q] = e;
    }
}

// ---------------- kernel E: per-node insertion sort (determinism) ----------------
__global__ void k_sort() {
    int idx = blockIdx.x * blockDim.x + threadIdx.x;
    if (idx >= 2 * N_NODES) return;
    int n = idx & (N_NODES - 1);
    bool isdst = idx >= N_NODES;
    int* list = isdst ? g_dst_list : g_src_list;
    int off = isdst ? g_dst_off[n] : g_src_off[n];
    int cnt = isdst ? g_dst_cnt[n] : g_src_cnt[n];
    for (int i = off + 1; i < off + cnt; i++) {
        int key = list[i];
        int j = i - 1;
        while (j >= off && list[j] > key) { list[j + 1] = list[j]; j--; }
        list[j + 1] = key;
    }
}

// ---------------- kernel F: main compute — one warp per row b ----------------
__global__ void __launch_bounds__(256)
k_compute(const int* __restrict__ edge_src, const int* __restrict__ edge_dst,
          const int* __restrict__ nbr, const int* __restrict__ nbr2rel,
          const float* __restrict__ rel_emb, const float* __restrict__ W1,
          const float* __restrict__ b1, float* __restrict__ out) {
    __shared__ float sW[6 * 32 * 32];   // transposed: sW[i*1024 + k*32 + d] = W1[i][d][k]
    __shared__ float sB[6 * 32];
    int tid = threadIdx.x;
    for (int idx = tid; idx < 6 * 32 * 32; idx += blockDim.x) {
        int i = idx >> 10, r = idx & 1023, d = r >> 5, k = r & 31;
        sW[i * 1024 + k * 32 + d] = W1[idx];
    }
    for (int idx = tid; idx < 6 * 32; idx += blockDim.x) sB[idx] = b1[idx];
    __syncthreads();

    int warp = tid >> 5, lane = tid & 31;
    int b = blockIdx.x * (blockDim.x >> 5) + warp;
    if (b >= B_ROWS) return;

    int eb = nbr[b];
    int u = edge_src[eb], v = edge_dst[eb];
    float x = rel_emb[nbr2rel[b] * D + lane];

    // per-mode candidate lists
    int so_u = g_src_off[u], sc_u = g_src_cnt[u];
    int so_v = g_src_off[v], sc_v = g_src_cnt[v];
    int do_u = g_dst_off[u], dc_u = g_dst_cnt[u];
    int do_v = g_dst_off[v], dc_v = g_dst_cnt[v];

    int   l_off[6] = { do_u, so_u, do_v, so_v, so_u, so_v };
    int   l_cnt[6] = { dc_u, sc_u, dc_v, sc_v, sc_u, sc_v };

    float agg = 0.f;
    #pragma unroll
    for (int i = 0; i < 6; i++) {
        const int* list = (i == 0 || i == 2) ? g_dst_list : g_src_list;
        int s0 = l_off[i], s1 = l_off[i] + l_cnt[i];
        float m = -1e38f, l = 0.f, t = 0.f;
        int cnt = 0;
        for (int j = s0; j < s1; j++) {
            int eid = __ldg(&list[j]);
            int es  = __ldg(&edge_src[eid]);
            int ed  = __ldg(&edge_dst[eid]);
            bool ok;
            switch (i) {
                case 0: ok = (es != v); break;  // dst==u guaranteed by list
                case 1: ok = (ed != v); break;  // src==u
                case 2: ok = (es != u); break;  // dst==v
                case 3: ok = (ed != u); break;  // src==v
                case 4: ok = (ed == v); break;  // src==u
                default: ok = (ed == u); break; // src==v
            }
            if (!ok) continue;
            float h = g_h0[eid * D + lane];
            float p = x * h;
            #pragma unroll
            for (int o = 16; o; o >>= 1) p += __shfl_xor_sync(FULL, p, o);
            if (p == 0.f) continue;                 // masked_fill: att==0 excluded
            float sc = p > 0.f ? p : 0.2f * p;      // leaky_relu(0.2)
            if (sc > m) {
                float scale = expf(m - sc);         // expf(-1e38-x)=0 on first hit
                l = l * scale + 1.f;
                t = t * scale + h;
                m = sc;
            } else {
                float wgt = expf(sc - m);
                l += wgt;
                t += wgt * h;
            }
            cnt++;
        }
        if (cnt > 0) {
            float tn = t / l;                       // softmax-weighted mean of h0
            const float* wbase = &sW[i * 1024];
            float acc = sB[i * 32 + lane];
            #pragma unroll
            for (int k = 0; k < 32; k++) {
                float tk = __shfl_sync(FULL, tn, k);
                acc += tk * wbase[k * 32 + lane];   // bank-conflict-free
            }
            agg += acc;
        }
    }
    float hN = agg > 0.f ? agg : 0.f;               // relu
    // neighbor_edges are distinct -> no race; out row already holds h0
    out[eb * D + lane] += hN;
}

// ---------------- launcher ----------------
extern "C" void kernel_launch(void* const* d_in, const int* in_sizes, int n_in,
                              void* d_out, int out_size) {
    const int*   edge_src  = (const int*)d_in[0];
    const int*   edge_dst  = (const int*)d_in[1];
    const int*   edge_type = (const int*)d_in[2];
    const int*   nbr       = (const int*)d_in[3];
    const int*   nbr2rel   = (const int*)d_in[4];
    const float* rel_emb   = (const float*)d_in[5];
    const float* W1        = (const float*)d_in[6];
    const float* b1        = (const float*)d_in[7];
    float* out = (float*)d_out;

    k_init<<<(E_EDGES * D + 255) / 256, 256>>>(edge_type, rel_emb, out);
    k_count<<<(E_EDGES + 255) / 256, 256>>>(edge_src, edge_dst);
    k_scan<<<1, 1024>>>();
    k_fill<<<(E_EDGES + 255) / 256, 256>>>(edge_src, edge_dst);
    k_sort<<<(2 * N_NODES + 255) / 256, 256>>>();
    k_compute<<<(B_ROWS / 8), 256>>>(edge_src, edge_dst, nbr, nbr2rel,
                                     rel_emb, W1, b1, out);
}

// round 2
// speedup vs baseline: 1.4785x; 1.4785x over previous
#include <cuda_runtime.h>

#define N_NODES 4096
#define NUM_REL 200
#define D 32
#define E_EDGES 16384
#define B_ROWS 2048
#define CAP 64
#define FULL 0xffffffffu

// ---------------- persistent scratch (no allocation allowed) ----------------
__device__ float g_h0[E_EDGES * D];
__device__ int4  g_edge[E_EDGES];              // (src, dst, type, 0)
__device__ int   g_cnt[2 * N_NODES];           // cursors; MUST be 0 on kernel_launch entry
__device__ int   g_cnt2[2 * N_NODES];          // consumer-visible counts
__device__ int   g_list[2 * N_NODES * CAP];    // src buckets then dst buckets
__device__ float g_R[NUM_REL * NUM_REL];       // rel Gram matrix

// ============ K1: h0/out copy (float4) + bucket fill + edge packing ============
__global__ void k_init(const int* __restrict__ edge_src, const int* __restrict__ edge_dst,
                       const int* __restrict__ edge_type, const float* __restrict__ rel_emb,
                       float* __restrict__ out) {
    int idx = blockIdx.x * blockDim.x + threadIdx.x;      // E*D/4 = 131072 threads
    if (idx < E_EDGES * D / 4) {
        int e = idx >> 3;                                  // 8 float4 per D=32 row
        int t = __ldg(&edge_type[e]);
        float4 val = ((const float4*)rel_emb)[t * 8 + (idx & 7)];
        ((float4*)g_h0)[idx] = val;
        ((float4*)out)[idx]  = val;
    }
    if (idx < E_EDGES) {
        int s = edge_src[idx], d0 = edge_dst[idx], t = edge_type[idx];
        g_edge[idx] = make_int4(s, d0, t, 0);
        int p = atomicAdd(&g_cnt[s], 1);
        if (p < CAP) g_list[s * CAP + p] = idx;
        int q = atomicAdd(&g_cnt[N_NODES + d0], 1);
        if (q < CAP) g_list[(N_NODES + d0) * CAP + q] = idx;
    }
}

// ====== K2: per-bucket sort (determinism) + cursor reset + Gram precompute ======
__global__ void k_prep(const float* __restrict__ rel_emb) {
    int idx = blockIdx.x * blockDim.x + threadIdx.x;
    if (idx < 2 * N_NODES) {
        int c = g_cnt[idx];
        if (c > CAP) c = CAP;
        g_cnt2[idx] = c;
        g_cnt[idx] = 0;                                    // restore invariant for next call
        int* list = &g_list[idx * CAP];
        for (int i = 1; i < c; i++) {                      // insertion sort (avg len 4)
            int key = list[i], j = i - 1;
            while (j >= 0 && list[j] > key) { list[j + 1] = list[j]; j--; }
            list[j + 1] = key;
        }
    }
    int g = idx - 2 * N_NODES;
    if (g >= 0 && g < NUM_REL * NUM_REL) {
        int a = g / NUM_REL, b = g - a * NUM_REL;
        const float4* ra = (const float4*)&rel_emb[a * D];
        const float4* rb = (const float4*)&rel_emb[b * D];
        float s = 0.f;
        #pragma unroll
        for (int k = 0; k < 8; k++) {
            float4 x = __ldg(&ra[k]), y = __ldg(&rb[k]);
            s += x.x * y.x + x.y * y.y + x.z * y.z + x.w * y.w;
        }
        g_R[g] = s;
    }
}

// online-softmax update on named registers (no local-mem array indexing)
#define UPD(M, L, T, C) {                                           \
    float _d = sc - M;                                              \
    if (_d > 0.f) { float _s = __expf(-_d); L = L * _s + 1.f; T = T * _s + h; M = sc; } \
    else          { float _w = __expf(_d);  L += _w;  T += _w * h; }                    \
    C++; }

// ============ K3: main compute — one warp per row b ============
__global__ void __launch_bounds__(256)
k_compute(const int* __restrict__ nbr, const int* __restrict__ n2r,
          const float* __restrict__ W1, const float* __restrict__ b1,
          float* __restrict__ out) {
    __shared__ float sW[6 * 32 * 32];   // sW[i*1024 + k*32 + d] = W1[i][d][k]
    __shared__ float sB[6 * 32];
    int tid = threadIdx.x;
    for (int idx = tid; idx < 6 * 32 * 32; idx += blockDim.x) {
        int i = idx >> 10, r = idx & 1023, d = r >> 5, k = r & 31;
        sW[i * 1024 + k * 32 + d] = W1[idx];
    }
    for (int idx = tid; idx < 6 * 32; idx += blockDim.x) sB[idx] = b1[idx];
    __syncthreads();

    int warp = tid >> 5, lane = tid & 31;
    int b = blockIdx.x * (blockDim.x >> 5) + warp;
    if (b >= B_ROWS) return;

    int eb = nbr[b];
    int4 ebd = g_edge[eb];
    int u = ebd.x, v = ebd.y;
    const float* Rrow = &g_R[n2r[b] * NUM_REL];

    float m0=-1e38f,l0=0,t0=0; int c0=0;  float m1=-1e38f,l1=0,t1=0; int c1=0;
    float m2=-1e38f,l2=0,t2=0; int c2=0;  float m3=-1e38f,l3=0,t3=0; int c3=0;
    float m4=-1e38f,l4=0,t4=0; int c4=0;  float m5=-1e38f,l5=0,t5=0; int c5=0;

    // pass A: out-edges of u (src==u): dst==v -> mode4 else mode1
    {
        int cnt = g_cnt2[u]; const int* list = &g_list[u * CAP];
        for (int j = 0; j < cnt; j++) {
            int eid = __ldg(&list[j]);
            int4 E = g_edge[eid];
            float sraw = Rrow[E.z];
            if (sraw == 0.f) continue;
            float sc = sraw > 0.f ? sraw : 0.2f * sraw;
            float h = g_h0[(eid << 5) | lane];
            if (E.y == v) UPD(m4, l4, t4, c4) else UPD(m1, l1, t1, c1)
        }
    }
    // pass B: out-edges of v (src==v): dst==u -> mode5 else mode3
    {
        int cnt = g_cnt2[v]; const int* list = &g_list[v * CAP];
        for (int j = 0; j < cnt; j++) {
            int eid = __ldg(&list[j]);
            int4 E = g_edge[eid];
            float sraw = Rrow[E.z];
            if (sraw == 0.f) continue;
            float sc = sraw > 0.f ? sraw : 0.2f * sraw;
            float h = g_h0[(eid << 5) | lane];
            if (E.y == u) UPD(m5, l5, t5, c5) else UPD(m3, l3, t3, c3)
        }
    }
    // pass C: in-edges of u (dst==u): src!=v -> mode0 (src==v handled as mode5)
    {
        int cnt = g_cnt2[N_NODES + u]; const int* list = &g_list[(N_NODES + u) * CAP];
        for (int j = 0; j < cnt; j++) {
            int eid = __ldg(&list[j]);
            int4 E = g_edge[eid];
            if (E.x == v) continue;
            float sraw = Rrow[E.z];
            if (sraw == 0.f) continue;
            float sc = sraw > 0.f ? sraw : 0.2f * sraw;
            float h = g_h0[(eid << 5) | lane];
            UPD(m0, l0, t0, c0)
        }
    }
    // pass D: in-edges of v (dst==v): src!=u -> mode2 (src==u handled as mode4)
    {
        int cnt = g_cnt2[N_NODES + v]; const int* list = &g_list[(N_NODES + v) * CAP];
        for (int j = 0; j < cnt; j++) {
            int eid = __ldg(&list[j]);
            int4 E = g_edge[eid];
            if (E.x == u) continue;
            float sraw = Rrow[E.z];
            if (sraw == 0.f) continue;
            float sc = sraw > 0.f ? sraw : 0.2f * sraw;
            float h = g_h0[(eid << 5) | lane];
            UPD(m2, l2, t2, c2)
        }
    }

    float agg = 0.f;
    #define EMIT(MI, LI, TI, CI, IDX) \
        if (CI > 0) {                                                       \
            float tn = TI / LI;                                             \
            const float* wb = &sW[IDX * 1024];                              \
            float acc = sB[IDX * 32 + lane];                                \
            _Pragma("unroll")                                               \
            for (int k = 0; k < 32; k++)                                    \
                acc += __shfl_sync(FULL, tn, k) * wb[k * 32 + lane];        \
            agg += acc;                                                     \
        }
    EMIT(m0, l0, t0, c0, 0)
    EMIT(m1, l1, t1, c1, 1)
    EMIT(m2, l2, t2, c2, 2)
    EMIT(m3, l3, t3, c3, 3)
    EMIT(m4, l4, t4, c4, 4)
    EMIT(m5, l5, t5, c5, 5)

    float hN = agg > 0.f ? agg : 0.f;
    out[(eb << 5) | lane] += hN;     // distinct eb per row -> no race; row holds h0
}

// ---------------- launcher: 3 kernels ----------------
extern "C" void kernel_launch(void* const* d_in, const int* in_sizes, int n_in,
                              void* d_out, int out_size) {
    const int*   edge_src  = (const int*)d_in[0];
    const int*   edge_dst  = (const int*)d_in[1];
    const int*   edge_type = (const int*)d_in[2];
    const int*   nbr       = (const int*)d_in[3];
    const int*   n2r       = (const int*)d_in[4];
    const float* rel_emb   = (const float*)d_in[5];
    const float* W1        = (const float*)d_in[6];
    const float* b1        = (const float*)d_in[7];
    float* out = (float*)d_out;

    k_init<<<(E_EDGES * D / 4 + 255) / 256, 256>>>(edge_src, edge_dst, edge_type,
                                                   rel_emb, out);
    k_prep<<<(2 * N_NODES + NUM_REL * NUM_REL + 255) / 256, 256>>>(rel_emb);
    k_compute<<<B_ROWS / 8, 256>>>(nbr, n2r, W1, b1, out);
}

// round 3
// speedup vs baseline: 1.7284x; 1.1691x over previous
#include <cuda_runtime.h>

#define N_NODES 4096
#define NUM_REL 200
#define D 32
#define E_EDGES 16384
#define B_ROWS 2048
#define CAP 64
#define FULL 0xffffffffu
#define GRID_BLOCKS 148
#define BLOCK_THREADS 512

// ---------------- persistent scratch (no allocation allowed) ----------------
__device__ float g_h0[E_EDGES * D];
__device__ int4  g_edge[E_EDGES];              // (src, dst, type, 0)
__device__ int   g_cnt[2 * N_NODES];           // cursors; zero on entry (self-restored)
__device__ int   g_cnt2[2 * N_NODES];          // clamped counts for compute phase
__device__ int   g_list[2 * N_NODES * CAP];    // src buckets then dst buckets
__device__ float g_R[NUM_REL * NUM_REL];       // rel Gram matrix
__device__ int   g_bar_cnt = 0;
__device__ int   g_bar_sense = 0;

// sense-reversing grid barrier; all GRID_BLOCKS blocks are co-resident by construction
__device__ __forceinline__ void grid_bar(int want) {
    __syncthreads();
    if (threadIdx.x == 0) {
        __threadfence();
        int t = atomicAdd(&g_bar_cnt, 1);
        if (t == GRID_BLOCKS - 1) {
            atomicExch(&g_bar_cnt, 0);
            __threadfence();
            atomicExch(&g_bar_sense, want);          // release
        } else {
            while (atomicAdd(&g_bar_sense, 0) != want) __nanosleep(32);
            __threadfence();                          // acquire
        }
    }
    __syncthreads();
}

// online-softmax update on named registers
#define UPD(M, L, T, C) {                                                               \
    float _d = sc - M;                                                                  \
    if (_d > 0.f) { float _s = __expf(-_d); L = L * _s + 1.f; T = T * _s + h; M = sc; } \
    else          { float _w = __expf(_d);  L += _w;  T += _w * h; }                    \
    C++; }

__global__ void __launch_bounds__(BLOCK_THREADS)
k_fused(const int* __restrict__ edge_src, const int* __restrict__ edge_dst,
        const int* __restrict__ edge_type, const int* __restrict__ nbr,
        const int* __restrict__ n2r, const float* __restrict__ rel_emb,
        const float* __restrict__ W1, const float* __restrict__ b1,
        float* __restrict__ out) {
    __shared__ float sW[6 * 32 * 32];   // sW[i*1024 + k*32 + d] = W1[i][d][k]
    __shared__ float sB[6 * 32];
    const int tid  = threadIdx.x;
    const int gtid = blockIdx.x * BLOCK_THREADS + tid;
    const int NTH  = GRID_BLOCKS * BLOCK_THREADS;     // 75776

    // smem weight staging (overlaps phase A)
    for (int idx = tid; idx < 6 * 32 * 32; idx += BLOCK_THREADS) {
        int i = idx >> 10, r = idx & 1023, d = r >> 5, k = r & 31;
        sW[i * 1024 + k * 32 + d] = W1[idx];
    }
    for (int idx = tid; idx < 6 * 32; idx += BLOCK_THREADS) sB[idx] = b1[idx];

    // ---------- Phase A ----------
    // A1: h0 + out copy (float4), E*D/4 = 131072 elements
    for (int idx = gtid; idx < E_EDGES * D / 4; idx += NTH) {
        int e = idx >> 3;
        int t = __ldg(&edge_type[e]);
        float4 val = __ldg(&((const float4*)rel_emb)[t * 8 + (idx & 7)]);
        ((float4*)g_h0)[idx] = val;
        ((float4*)out)[idx]  = val;
    }
    // A2: edge packing + bucket fill
    if (gtid < E_EDGES) {
        int s = edge_src[gtid], d0 = edge_dst[gtid], t = edge_type[gtid];
        g_edge[gtid] = make_int4(s, d0, t, 0);
        int p = atomicAdd(&g_cnt[s], 1);
        if (p < CAP) g_list[s * CAP + p] = gtid;
        int q = atomicAdd(&g_cnt[N_NODES + d0], 1);
        if (q < CAP) g_list[(N_NODES + d0) * CAP + q] = gtid;
    }
    // A3: relation Gram matrix (40000 dot products, rel_emb is L2-resident)
    for (int g = gtid; g < NUM_REL * NUM_REL; g += NTH) {
        int a = g / NUM_REL, bb = g - a * NUM_REL;
        const float4* ra = (const float4*)&rel_emb[a * D];
        const float4* rb = (const float4*)&rel_emb[bb * D];
        float s = 0.f;
        #pragma unroll
        for (int k = 0; k < 8; k++) {
            float4 x = __ldg(&ra[k]), y = __ldg(&rb[k]);
            s += x.x * y.x + x.y * y.y + x.z * y.z + x.w * y.w;
        }
        g_R[g] = s;
    }

    grid_bar(1);

    // ---------- Phase B1: publish counts, reset cursors ----------
    for (int idx = gtid; idx < 2 * N_NODES; idx += NTH) {
        int c = g_cnt[idx];
        g_cnt2[idx] = c > CAP ? CAP : c;
        g_cnt[idx] = 0;
    }

    grid_bar(0);

    // ---------- Phase B2: one warp per row b ----------
    const int lane = tid & 31;
    const int b = (gtid >> 5);
    if (b >= B_ROWS) return;

    int eb = nbr[b];
    int4 ebd = g_edge[eb];
    int u = ebd.x, v = ebd.y;
    const float* Rrow = &g_R[n2r[b] * NUM_REL];

    float m0=-1e38f,l0=0,t0=0; int c0=0;  float m1=-1e38f,l1=0,t1=0; int c1=0;
    float m2=-1e38f,l2=0,t2=0; int c2=0;  float m3=-1e38f,l3=0,t3=0; int c3=0;
    float m4=-1e38f,l4=0,t4=0; int c4=0;  float m5=-1e38f,l5=0,t5=0; int c5=0;

    // pass A: out-edges of u (src==u): dst==v -> mode4 else mode1
    {
        int cnt = g_cnt2[u]; const int* list = &g_list[u * CAP];
        for (int j = 0; j < cnt; j++) {
            int eid = __ldg(&list[j]);
            int4 E = g_edge[eid];
            float sraw = Rrow[E.z];
            if (sraw == 0.f) continue;
            float sc = sraw > 0.f ? sraw : 0.2f * sraw;
            float h = g_h0[(eid << 5) | lane];
            if (E.y == v) UPD(m4, l4, t4, c4) else UPD(m1, l1, t1, c1)
        }
    }
    // pass B: out-edges of v (src==v): dst==u -> mode5 else mode3
    {
        int cnt = g_cnt2[v]; const int* list = &g_list[v * CAP];
        for (int j = 0; j < cnt; j++) {
            int eid = __ldg(&list[j]);
            int4 E = g_edge[eid];
            float sraw = Rrow[E.z];
            if (sraw == 0.f) continue;
            float sc = sraw > 0.f ? sraw : 0.2f * sraw;
            float h = g_h0[(eid << 5) | lane];
            if (E.y == u) UPD(m5, l5, t5, c5) else UPD(m3, l3, t3, c3)
        }
    }
    // pass C: in-edges of u (dst==u): src!=v -> mode0 (src==v covered by mode5 removal)
    {
        int cnt = g_cnt2[N_NODES + u]; const int* list = &g_list[(N_NODES + u) * CAP];
        for (int j = 0; j < cnt; j++) {
            int eid = __ldg(&list[j]);
            int4 E = g_edge[eid];
            if (E.x == v) continue;
            float sraw = Rrow[E.z];
            if (sraw == 0.f) continue;
            float sc = sraw > 0.f ? sraw : 0.2f * sraw;
            float h = g_h0[(eid << 5) | lane];
            UPD(m0, l0, t0, c0)
        }
    }
    // pass D: in-edges of v (dst==v): src!=u -> mode2 (src==u covered by mode4 removal)
    {
        int cnt = g_cnt2[N_NODES + v]; const int* list = &g_list[(N_NODES + v) * CAP];
        for (int j = 0; j < cnt; j++) {
            int eid = __ldg(&list[j]);
            int4 E = g_edge[eid];
            if (E.x == u) continue;
            float sraw = Rrow[E.z];
            if (sraw == 0.f) continue;
            float sc = sraw > 0.f ? sraw : 0.2f * sraw;
            float h = g_h0[(eid << 5) | lane];
            UPD(m2, l2, t2, c2)
        }
    }

    float agg = 0.f;
    #define EMIT(MI, LI, TI, CI, IDX)                                       \
        if (CI > 0) {                                                       \
            float tn = TI / LI;                                             \
            const float* wb = &sW[IDX * 1024];                              \
            float acc = sB[IDX * 32 + lane];                                \
            _Pragma("unroll")                                               \
            for (int k = 0; k < 32; k++)                                    \
                acc += __shfl_sync(FULL, tn, k) * wb[k * 32 + lane];        \
            agg += acc;                                                     \
        }
    EMIT(m0, l0, t0, c0, 0)
    EMIT(m1, l1, t1, c1, 1)
    EMIT(m2, l2, t2, c2, 2)
    EMIT(m3, l3, t3, c3, 3)
    EMIT(m4, l4, t4, c4, 4)
    EMIT(m5, l5, t5, c5, 5)

    float hN = agg > 0.f ? agg : 0.f;
    out[(eb << 5) | lane] += hN;     // distinct eb per row -> no race; row holds h0
}

// ---------------- launcher: ONE kernel ----------------
extern "C" void kernel_launch(void* const* d_in, const int* in_sizes, int n_in,
                              void* d_out, int out_size) {
    const int*   edge_src  = (const int*)d_in[0];
    const int*   edge_dst  = (const int*)d_in[1];
    const int*   edge_type = (const int*)d_in[2];
    const int*   nbr       = (const int*)d_in[3];
    const int*   n2r       = (const int*)d_in[4];
    const float* rel_emb   = (const float*)d_in[5];
    const float* W1        = (const float*)d_in[6];
    const float* b1        = (const float*)d_in[7];
    float* out = (float*)d_out;

    k_fused<<<GRID_BLOCKS, BLOCK_THREADS>>>(edge_src, edge_dst, edge_type,
                                            nbr, n2r, rel_emb, W1, b1, out);
}

// round 4
// speedup vs baseline: 2.6694x; 1.5444x over previous
#include <cuda_runtime.h>

#define N_NODES 4096
#define NUM_REL 200
#define D 32
#define E_EDGES 16384
#define B_ROWS 2048
#define CAP 64
#define FULL 0xffffffffu
#define GRID_BLOCKS 148
#define BLOCK_THREADS 512
#define NTH (GRID_BLOCKS * BLOCK_THREADS)

// ---------------- persistent scratch (no allocation) ----------------
__device__ int      g_cnt[2][2 * N_NODES];      // ping-pong by epoch parity (zero-initialized)
__device__ int      g_list[2 * N_NODES * CAP];  // packed (other<<8)|type
__device__ int4     g_row[B_ROWS];              // (u, v, relb, eb)
__device__ unsigned g_epoch = 0;
__device__ int      g_bar_cnt = 0;

__device__ __forceinline__ unsigned ld_acq(const unsigned* p) {
    unsigned v;
    asm volatile("ld.acquire.gpu.u32 %0, [%1];" : "=r"(v) : "l"(p) : "memory");
    return v;
}

// merge one chunk's masked score set into running (m,l,t,c); mask warp-uniform
#define MERGE(mask, M, L, T, C)                                              \
    if (mask) {                                                              \
        bool _in = (mask >> lane) & 1;                                       \
        float _v = _in ? sc : -1e38f;                                        \
        _Pragma("unroll")                                                    \
        for (int _o = 16; _o; _o >>= 1)                                      \
            _v = fmaxf(_v, __shfl_xor_sync(FULL, _v, _o));                   \
        float _mn = fmaxf(M, _v);                                            \
        float _w = _in ? __expf(sc - _mn) : 0.f;                             \
        float _ws = _w;                                                      \
        _Pragma("unroll")                                                    \
        for (int _o = 16; _o; _o >>= 1) _ws += __shfl_xor_sync(FULL, _ws, _o); \
        float _scale = __expf(M - _mn);                                      \
        L = L * _scale + _ws;                                                \
        T = T * _scale;                                                      \
        unsigned _mm = mask;                                                 \
        while (_mm) {                                                        \
            int _j = __ffs(_mm) - 1; _mm &= _mm - 1;                         \
            float _wj = __shfl_sync(FULL, _w, _j);                           \
            int _tyj = __shfl_sync(FULL, ty, _j);                            \
            T += _wj * srel[_tyj * 33 + lane];                               \
        }                                                                    \
        M = _mn;                                                             \
        C += __popc(mask);                                                   \
    }

// one bucket pass: classify into match-mode (if use_match) / else-mode
#define PASS(CNT, LISTBASE, MATCHNODE, USE_MATCH, mM, lM, tM, cM, mE, lE, tE, cE) \
    for (int _base = 0; _base < (CNT); _base += 32) {                        \
        int _j = _base + lane;                                               \
        bool _valid = _j < (CNT);                                            \
        int _packed = _valid ? __ldg(&g_list[(LISTBASE) + _j]) : 0;          \
        int ty = _packed & 255;                                              \
        int _other = _packed >> 8;                                           \
        float _p = 0.f;                                                      \
        _Pragma("unroll")                                                    \
        for (int _d = 0; _d < 32; _d++) _p += xr[_d] * srel[ty * 33 + _d];   \
        bool _part = _valid && (_p != 0.f);                                  \
        float sc = _p > 0.f ? _p : 0.2f * _p;                                \
        bool _ism = (_other == (MATCHNODE));                                 \
        unsigned _maskM = __ballot_sync(FULL, _part && _ism && (USE_MATCH)); \
        unsigned _maskE = __ballot_sync(FULL, _part && !_ism);               \
        MERGE(_maskM, mM, lM, tM, cM)                                        \
        MERGE(_maskE, mE, lE, tE, cE)                                        \
    }

__global__ void __launch_bounds__(BLOCK_THREADS, 1)
k_fused(const int* __restrict__ edge_src, const int* __restrict__ edge_dst,
        const int* __restrict__ edge_type, const int* __restrict__ nbr,
        const int* __restrict__ n2r, const float* __restrict__ rel_emb,
        const float* __restrict__ W1, const float* __restrict__ b1,
        float* __restrict__ out) {
    extern __shared__ float smem[];
    float* srel = smem;            // [200*33] padded, conflict-free
    float* sW   = smem + 6600;     // [6*32*32] transposed: sW[i*1024+k*32+d]=W1[i][d][k]
    float* sB   = smem + 12744;    // [6*32]

    const int tid  = threadIdx.x;
    const int gtid = blockIdx.x * BLOCK_THREADS + tid;

    const unsigned ep0 = ld_acq(&g_epoch);   // stable at launch: all arrivals gate the bump
    int* cntA = g_cnt[ep0 & 1];               // zeroed by previous launch (or static init)
    int* cntZ = g_cnt[(ep0 & 1) ^ 1];

    // ---- smem staging ----
    for (int idx = tid; idx < NUM_REL * D; idx += BLOCK_THREADS) {
        int t = idx >> 5, d = idx & 31;
        srel[t * 33 + d] = __ldg(&rel_emb[idx]);
    }
    for (int idx = tid; idx < 6 * 32 * 32; idx += BLOCK_THREADS) {
        int i = idx >> 10, r = idx & 1023, d = r >> 5, k = r & 31;
        sW[i * 1024 + k * 32 + d] = __ldg(&W1[idx]);
    }
    for (int idx = tid; idx < 6 * 32; idx += BLOCK_THREADS) sB[idx] = __ldg(&b1[idx]);

    // ---- Phase A ----
    // A1: out = h0 gather (float4)
    for (int idx = gtid; idx < E_EDGES * D / 4; idx += NTH) {
        int e = idx >> 3;
        int t = __ldg(&edge_type[e]);
        ((float4*)out)[idx] = __ldg(&((const float4*)rel_emb)[t * 8 + (idx & 7)]);
    }
    // A2: bucket fill with packed entries
    if (gtid < E_EDGES) {
        int s = edge_src[gtid], d0 = edge_dst[gtid], t = edge_type[gtid];
        int p = atomicAdd(&cntA[s], 1);
        if (p < CAP) g_list[s * CAP + p] = (d0 << 8) | t;
        int q = atomicAdd(&cntA[N_NODES + d0], 1);
        if (q < CAP) g_list[(N_NODES + d0) * CAP + q] = (s << 8) | t;
    }
    // A3: zero the other parity's counters for the NEXT launch
    for (int idx = gtid; idx < 2 * N_NODES; idx += NTH) cntZ[idx] = 0;
    // A4: per-row metadata
    if (gtid < B_ROWS) {
        int eb = __ldg(&nbr[gtid]);
        g_row[gtid] = make_int4(__ldg(&edge_src[eb]), __ldg(&edge_dst[eb]),
                                __ldg(&n2r[gtid]), eb);
    }

    // ---- single grid barrier (all 148 blocks co-resident: 1 block/SM) ----
    __syncthreads();
    if (tid == 0) {
        __threadfence();
        if (atomicAdd(&g_bar_cnt, 1) == GRID_BLOCKS - 1) {
            atomicExch(&g_bar_cnt, 0);
            __threadfence();
            atomicAdd(&g_epoch, 1);             // release: epoch -> ep0+1
        } else {
            while (ld_acq(&g_epoch) == ep0) __nanosleep(64);
        }
    }
    __syncthreads();

    // ---- Phase B: one warp per row ----
    const int lane = tid & 31;
    const int b = gtid >> 5;
    if (b >= B_ROWS) return;

    int4 row = g_row[b];
    int u = row.x, v = row.y, eb = row.w;
    const float* xr = &srel[row.z * 33];

    // prefetch the 4 bucket counts together (independent L2 loads)
    int cu  = min(cntA[u], CAP);
    int cv  = min(cntA[v], CAP);
    int cdu = min(cntA[N_NODES + u], CAP);
    int cdv = min(cntA[N_NODES + v], CAP);

    float m0=-1e38f,l0=0,t0=0; int c0=0;  float m1=-1e38f,l1=0,t1=0; int c1=0;
    float m2=-1e38f,l2=0,t2=0; int c2=0;  float m3=-1e38f,l3=0,t3=0; int c3=0;
    float m4=-1e38f,l4=0,t4=0; int c4=0;  float m5=-1e38f,l5=0,t5=0; int c5=0;
    float dum_m=-1e38f, dum_l=0, dum_t=0; int dum_c=0;  // sink for skipped modes

    // src-bucket of u: other==v -> mode4 else mode1
    PASS(cu,  u * CAP,               v, true,  m4,l4,t4,c4, m1,l1,t1,c1)
    // src-bucket of v: other==u -> mode5 else mode3
    PASS(cv,  v * CAP,               u, true,  m5,l5,t5,c5, m3,l3,t3,c3)
    // dst-bucket of u: other==v -> skip (mode6 dealt via mode5) else mode0
    PASS(cdu, (N_NODES + u) * CAP,   v, false, dum_m,dum_l,dum_t,dum_c, m0,l0,t0,c0)
    // dst-bucket of v: other==u -> skip else mode2
    PASS(cdv, (N_NODES + v) * CAP,   u, false, dum_m,dum_l,dum_t,dum_c, m2,l2,t2,c2)

    float agg = 0.f;
    #define EMIT(LI, TI, CI, IDX)                                            \
        if (CI > 0) {                                                        \
            float tn = TI / LI;                                              \
            const float* wb = &sW[IDX * 1024];                               \
            float acc = sB[IDX * 32 + lane];                                 \
            _Pragma("unroll")                                                \
            for (int k = 0; k < 32; k++)                                     \
                acc += __shfl_sync(FULL, tn, k) * wb[k * 32 + lane];         \
            agg += acc;                                                      \
        }
    EMIT(l0, t0, c0, 0)
    EMIT(l1, t1, c1, 1)
    EMIT(l2, t2, c2, 2)
    EMIT(l3, t3, c3, 3)
    EMIT(l4, t4, c4, 4)
    EMIT(l5, t5, c5, 5)

    float hN = agg > 0.f ? agg : 0.f;
    out[(eb << 5) | lane] += hN;     // distinct eb per row; row holds h0 from A1
}

// ---------------- launcher: ONE kernel, dynamic smem ----------------
extern "C" void kernel_launch(void* const* d_in, const int* in_sizes, int n_in,
                              void* d_out, int out_size) {
    const int*   edge_src  = (const int*)d_in[0];
    const int*   edge_dst  = (const int*)d_in[1];
    const int*   edge_type = (const int*)d_in[2];
    const int*   nbr       = (const int*)d_in[3];
    const int*   n2r       = (const int*)d_in[4];
    const float* rel_emb   = (const float*)d_in[5];
    const float* W1        = (const float*)d_in[6];
    const float* b1        = (const float*)d_in[7];
    float* out = (float*)d_out;

    const int SMEM_BYTES = (6600 + 6144 + 192) * 4;   // 51744
    cudaFuncSetAttribute(k_fused, cudaFuncAttributeMaxDynamicSharedMemorySize, SMEM_BYTES);
    k_fused<<<GRID_BLOCKS, BLOCK_THREADS, SMEM_BYTES>>>(
        edge_src, edge_dst, edge_type, nbr, n2r, rel_emb, W1, b1, out);
}

// round 5
// speedup vs baseline: 2.8946x; 1.0843x over previous
#include <cuda_runtime.h>

#define N_NODES 4096
#define NUM_REL 200
#define D 32
#define E_EDGES 16384
#define B_ROWS 2048
#define CAP 64
#define FULL 0xffffffffu
#define GRID_BLOCKS 128
#define BLOCK_THREADS 1024
#define NTH (GRID_BLOCKS * BLOCK_THREADS)   // 131072

// ---------------- persistent scratch (no allocation) ----------------
__device__ int      g_cnt[2][2 * N_NODES];      // ping-pong by epoch parity
__device__ int      g_list[2 * N_NODES * CAP];  // packed (other<<8)|type
__device__ int4     g_row[B_ROWS];              // (u, v, relb|(type_eb<<8), eb)
__device__ float    g_R[NUM_REL * NUM_REL];     // leaky_relu(rel_a . rel_b)
__device__ unsigned g_epoch = 0;
__device__ int      g_bar_cnt = 0;

__device__ __forceinline__ unsigned ld_acq(const unsigned* p) {
    unsigned v;
    asm volatile("ld.acquire.gpu.u32 %0, [%1];" : "=r"(v) : "l"(p) : "memory");
    return v;
}

// merge masked per-lane (sc,ty) into running (M,L,T,C); mask warp-uniform
#define MERGE(mask, SC, TY, M, L, T, C)                                        \
    if (mask) {                                                                \
        bool _in = (mask >> lane) & 1;                                         \
        float _v = _in ? (SC) : -1e38f;                                        \
        _Pragma("unroll")                                                      \
        for (int _o = 16; _o; _o >>= 1)                                        \
            _v = fmaxf(_v, __shfl_xor_sync(FULL, _v, _o));                     \
        float _mn = fmaxf(M, _v);                                              \
        float _w = _in ? __expf((SC) - _mn) : 0.f;                             \
        float _ws = _w;                                                        \
        _Pragma("unroll")                                                      \
        for (int _o = 16; _o; _o >>= 1) _ws += __shfl_xor_sync(FULL, _ws, _o); \
        float _scale = __expf(M - _mn);                                        \
        L = L * _scale + _ws;                                                  \
        T = T * _scale;                                                        \
        unsigned _mm = mask;                                                   \
        while (_mm) {                                                          \
            int _j = __ffs(_mm) - 1; _mm &= _mm - 1;                           \
            float _wj = __shfl_sync(FULL, _w, _j);                             \
            int _tyj = __shfl_sync(FULL, (TY), _j);                            \
            T += _wj * srel[_tyj * 33 + lane];                                 \
        }                                                                      \
        M = _mn;                                                               \
        C += __popc(mask);                                                     \
    }

// classify one chunk into match-mode / else-mode and merge
#define CHUNK(PK, SC, VALID, MATCHNODE, USE_MATCH, mM,lM,tM,cM, mE,lE,tE,cE)   \
    {                                                                          \
        int _ty = (PK) & 255;                                                  \
        int _other = (PK) >> 8;                                                \
        bool _part = (VALID) && ((SC) != 0.f);                                 \
        bool _ism = (_other == (MATCHNODE));                                   \
        unsigned _maskM = __ballot_sync(FULL, _part && _ism && (USE_MATCH));   \
        unsigned _maskE = __ballot_sync(FULL, _part && !_ism);                 \
        MERGE(_maskM, (SC), _ty, mM, lM, tM, cM)                               \
        MERGE(_maskE, (SC), _ty, mE, lE, tE, cE)                               \
    }

#define EMIT(LI, TI, CI, IDX)                                                  \
    if (CI > 0) {                                                              \
        float tn = TI / LI;                                                    \
        const float* wb = &sW[(IDX) * 1024];                                   \
        float acc = sB[(IDX) * 32 + lane];                                     \
        _Pragma("unroll")                                                      \
        for (int k = 0; k < 32; k++)                                           \
            acc += __shfl_sync(FULL, tn, k) * wb[k * 32 + lane];               \
        agg += acc;                                                            \
    }

__global__ void __launch_bounds__(BLOCK_THREADS, 1)
k_fused(const int* __restrict__ edge_src, const int* __restrict__ edge_dst,
        const int* __restrict__ edge_type, const int* __restrict__ nbr,
        const int* __restrict__ n2r, const float* __restrict__ rel_emb,
        const float* __restrict__ W1, const float* __restrict__ b1,
        float* __restrict__ out) {
    extern __shared__ float smem[];
    float* srel  = smem;             // [200*33] padded, conflict-free
    float* sW    = smem + 6600;      // [6*32*32] sW[i*1024+k*32+d]=W1[i][d][k]
    float* sB    = smem + 12744;     // [6*32]
    float* s_agg = smem + 12936;     // [16*32] odd-warp partial agg per row

    const int tid  = threadIdx.x;
    const int gtid = blockIdx.x * BLOCK_THREADS + tid;

    const unsigned ep0 = ld_acq(&g_epoch);
    int* cntA = g_cnt[ep0 & 1];
    int* cntZ = g_cnt[(ep0 & 1) ^ 1];

    // ---- smem staging ----
    for (int idx = tid; idx < NUM_REL * D; idx += BLOCK_THREADS) {
        int t = idx >> 5, d = idx & 31;
        srel[t * 33 + d] = __ldg(&rel_emb[idx]);
    }
    for (int idx = tid; idx < 6 * 32 * 32; idx += BLOCK_THREADS) {
        int i = idx >> 10, r = idx & 1023, d = r >> 5, k = r & 31;
        sW[i * 1024 + k * 32 + d] = __ldg(&W1[idx]);
    }
    if (tid < 6 * 32) sB[tid] = __ldg(&b1[tid]);
    __syncthreads();            // srel ready for Gram compute

    // ---- Phase A ----
    // A1: out = h0 gather (exactly one float4 per thread)
    {
        int idx = gtid;          // NTH == E*D/4 == 131072
        int e = idx >> 3;
        int t = __ldg(&edge_type[e]);
        ((float4*)out)[idx] = __ldg(&((const float4*)rel_emb)[t * 8 + (idx & 7)]);
    }
    // A2: bucket fill (packed entries)
    if (gtid < E_EDGES) {
        int s = edge_src[gtid], d0 = edge_dst[gtid], t = edge_type[gtid];
        int p = atomicAdd(&cntA[s], 1);
        if (p < CAP) g_list[s * CAP + p] = (d0 << 8) | t;
        int q = atomicAdd(&cntA[N_NODES + d0], 1);
        if (q < CAP) g_list[(N_NODES + d0) * CAP + q] = (s << 8) | t;
    }
    // A3: zero other parity for next launch
    if (gtid < 2 * N_NODES) cntZ[gtid] = 0;
    // A4: per-row metadata
    if (gtid < B_ROWS) {
        int eb = __ldg(&nbr[gtid]);
        int te = __ldg(&edge_type[eb]);
        g_row[gtid] = make_int4(__ldg(&edge_src[eb]), __ldg(&edge_dst[eb]),
                                __ldg(&n2r[gtid]) | (te << 8), eb);
    }
    // A5: Gram matrix with leaky_relu, evenly spread across blocks
    {
        int g = tid * GRID_BLOCKS + blockIdx.x;
        if (g < NUM_REL * NUM_REL) {
            int a = g / NUM_REL, bb = g - a * NUM_REL;
            float s = 0.f;
            #pragma unroll
            for (int d = 0; d < 32; d++) s += srel[a * 33 + d] * srel[bb * 33 + d];
            g_R[g] = s > 0.f ? s : 0.2f * s;
        }
    }

    // ---- single grid barrier (128 blocks, all co-resident) ----
    __syncthreads();
    if (tid == 0) {
        __threadfence();
        if (atomicAdd(&g_bar_cnt, 1) == GRID_BLOCKS - 1) {
            atomicExch(&g_bar_cnt, 0);
            __threadfence();
            atomicAdd(&g_epoch, 1);
        } else {
            while (ld_acq(&g_epoch) == ep0) __nanosleep(32);
        }
    }
    __syncthreads();

    // ---- Phase B: TWO warps per row ----
    const int lane = tid & 31;
    const int warp = tid >> 5;               // 0..31
    const int pairIdx = warp >> 1;           // 0..15
    const bool evenW = (warp & 1) == 0;
    const int b = blockIdx.x * 16 + pairIdx; // < 2048 always (128*16)

    int4 row = g_row[b];
    const int u = row.x, v = row.y, eb = row.w;
    const int relb = row.z & 255, tEb = (row.z >> 8) & 255;
    const float* Rrow = &g_R[relb * NUM_REL];

    float mA=-1e38f,lA=0,tA=0; int cA=0;   // even: mode4 | odd: (unused match sink)
    float mB=-1e38f,lB=0,tB=0; int cB=0;   // even: mode1 | odd: mode0
    float mC=-1e38f,lC=0,tC=0; int cC=0;   // even: mode5 | odd: sink
    float mD=-1e38f,lD=0,tD=0; int cD=0;   // even: mode3 | odd: mode2

    // bucket bases: even -> src buckets, odd -> dst buckets
    const int base1 = (evenW ? u : (N_NODES + u)) * CAP;
    const int base2 = (evenW ? v : (N_NODES + v)) * CAP;
    const int cnt1  = min(cntA[evenW ? u : (N_NODES + u)], CAP);
    const int cnt2  = min(cntA[evenW ? v : (N_NODES + v)], CAP);
    const bool useM = evenW;                 // odd warps skip matches entirely
    const int match1 = v, match2 = u;

    // prefetch chunk 0 of both buckets (independent chains, MLP=2)
    bool v1 = lane < cnt1, v2 = lane < cnt2;
    int pk1 = v1 ? __ldg(&g_list[base1 + lane]) : 0;
    int pk2 = v2 ? __ldg(&g_list[base2 + lane]) : 0;
    float sc1 = v1 ? __ldg(&Rrow[pk1 & 255]) : 0.f;
    float sc2 = v2 ? __ldg(&Rrow[pk2 & 255]) : 0.f;

    CHUNK(pk1, sc1, v1, match1, useM, mA,lA,tA,cA, mB,lB,tB,cB)
    for (int bs = 32; bs < cnt1; bs += 32) {          // rare overflow chunks
        int j = bs + lane; bool vv = j < cnt1;
        int pk = vv ? __ldg(&g_list[base1 + j]) : 0;
        float sc = vv ? __ldg(&Rrow[pk & 255]) : 0.f;
        CHUNK(pk, sc, vv, match1, useM, mA,lA,tA,cA, mB,lB,tB,cB)
    }
    CHUNK(pk2, sc2, v2, match2, useM, mC,lC,tC,cC, mD,lD,tD,cD)
    for (int bs = 32; bs < cnt2; bs += 32) {
        int j = bs + lane; bool vv = j < cnt2;
        int pk = vv ? __ldg(&g_list[base2 + j]) : 0;
        float sc = vv ? __ldg(&Rrow[pk & 255]) : 0.f;
        CHUNK(pk, sc, vv, match2, useM, mC,lC,tC,cC, mD,lD,tD,cD)
    }

    float agg = 0.f;
    if (evenW) {
        EMIT(lB, tB, cB, 1)   // mode1: src==u, dst!=v
        EMIT(lD, tD, cD, 3)   // mode3: src==v, dst!=u
        EMIT(lA, tA, cA, 4)   // mode4: src==u, dst==v
        EMIT(lC, tC, cC, 5)   // mode5: src==v, dst==u
    } else {
        EMIT(lB, tB, cB, 0)   // mode0: dst==u, src!=v
        EMIT(lD, tD, cD, 2)   // mode2: dst==v, src!=u
        s_agg[pairIdx * 32 + lane] = agg;
    }
    __syncthreads();
    if (evenW) {
        float tot = agg + s_agg[pairIdx * 32 + lane];
        float hN = tot > 0.f ? tot : 0.f;
        out[(eb << 5) | lane] = srel[tEb * 33 + lane] + hN;   // distinct eb rows
    }
}

// ---------------- launcher: ONE kernel ----------------
extern "C" void kernel_launch(void* const* d_in, const int* in_sizes, int n_in,
                              void* d_out, int out_size) {
    const int*   edge_src  = (const int*)d_in[0];
    const int*   edge_dst  = (const int*)d_in[1];
    const int*   edge_type = (const int*)d_in[2];
    const int*   nbr       = (const int*)d_in[3];
    const int*   n2r       = (const int*)d_in[4];
    const float* rel_emb   = (const float*)d_in[5];
    const float* W1        = (const float*)d_in[6];
    const float* b1        = (const float*)d_in[7];
    float* out = (float*)d_out;

    const int SMEM_BYTES = (6600 + 6144 + 192 + 512) * 4;   // 53792
    cudaFuncSetAttribute(k_fused, cudaFuncAttributeMaxDynamicSharedMemorySize, SMEM_BYTES);
    k_fused<<<GRID_BLOCKS, BLOCK_THREADS, SMEM_BYTES>>>(
        edge_src, edge_dst, edge_type, nbr, n2r, rel_emb, W1, b1, out);
}

// round 6
// speedup vs baseline: 3.2087x; 1.1085x over previous
#include <cuda_runtime.h>

#define N_NODES 4096
#define NUM_REL 200
#define D 32
#define E_EDGES 16384
#define B_ROWS 2048
#define CAP 64
#define FULL 0xffffffffu
#define GRID_BLOCKS 128
#define BLOCK_THREADS 1024
#define NTH (GRID_BLOCKS * BLOCK_THREADS)   // 131072

// ---------------- persistent scratch (no allocation) ----------------
__device__ int      g_cnt[2][2 * N_NODES];      // ping-pong by epoch parity
__device__ int      g_list[2 * N_NODES * CAP];  // packed (other<<8)|type
__device__ int4     g_row[B_ROWS];              // (u, v, relb|(type_eb<<8), eb)
__device__ float    g_R[NUM_REL * NUM_REL];     // leaky_relu(rel_a . rel_b)
__device__ float    g_Y[6 * NUM_REL * D];       // Y[i,t,:] = rel_emb[t] @ W1[i]^T
__device__ unsigned g_epoch = 0;
__device__ int      g_bar_cnt = 0;

__device__ __forceinline__ unsigned ld_acq(const unsigned* p) {
    unsigned v;
    asm volatile("ld.acquire.gpu.u32 %0, [%1];" : "=r"(v) : "l"(p) : "memory");
    return v;
}

// process one bucket: softmax over (match-mode, else-mode) + Y-gather into agg
#define BUCKET(BASE, CNT, MATCH, MODE_M, MODE_E, USE_M)                         \
{                                                                               \
    bool va = lane < (CNT);                                                     \
    bool vb = lane + 32 < (CNT);                                                \
    int pka = va ? __ldg(&g_list[(BASE) + lane]) : 0;                           \
    int pkb = vb ? __ldg(&g_list[(BASE) + lane + 32]) : 0;                      \
    float sca = va ? __ldg(&Rrow[pka & 255]) : 0.f;                             \
    float scb = vb ? __ldg(&Rrow[pkb & 255]) : 0.f;                             \
    bool ia = ((pka >> 8) == (MATCH));                                          \
    bool ib = ((pkb >> 8) == (MATCH));                                          \
    bool pMa = (USE_M) && va && ia && sca != 0.f;                               \
    bool pMb = (USE_M) && vb && ib && scb != 0.f;                               \
    bool pEa = va && !ia && sca != 0.f;                                         \
    bool pEb = vb && !ib && scb != 0.f;                                         \
    float mM = fmaxf(pMa ? sca : -1e38f, pMb ? scb : -1e38f);                   \
    float mE = fmaxf(pEa ? sca : -1e38f, pEb ? scb : -1e38f);                   \
    _Pragma("unroll")                                                           \
    for (int o = 16; o; o >>= 1) {                                              \
        mM = fmaxf(mM, __shfl_xor_sync(FULL, mM, o));                           \
        mE = fmaxf(mE, __shfl_xor_sync(FULL, mE, o));                           \
    }                                                                           \
    float eMa = pMa ? __expf(sca - mM) : 0.f;                                   \
    float eMb = pMb ? __expf(scb - mM) : 0.f;                                   \
    float eEa = pEa ? __expf(sca - mE) : 0.f;                                   \
    float eEb = pEb ? __expf(scb - mE) : 0.f;                                   \
    float LM = eMa + eMb, LE = eEa + eEb;                                       \
    _Pragma("unroll")                                                           \
    for (int o = 16; o; o >>= 1) {                                              \
        LM += __shfl_xor_sync(FULL, LM, o);                                     \
        LE += __shfl_xor_sync(FULL, LE, o);                                     \
    }                                                                           \
    float pa = pMa ? __fdividef(eMa, LM) : (pEa ? __fdividef(eEa, LE) : 0.f);   \
    float pb = pMb ? __fdividef(eMb, LM) : (pEb ? __fdividef(eEb, LE) : 0.f);   \
    int ya = ((ia ? (MODE_M) : (MODE_E)) * NUM_REL + (pka & 255)) << 5;         \
    int yb = ((ib ? (MODE_M) : (MODE_E)) * NUM_REL + (pkb & 255)) << 5;         \
    if (LE > 0.f) agg += sB[(MODE_E) * 32 + lane];                              \
    if ((USE_M) && LM > 0.f) agg += sB[(MODE_M) * 32 + lane];                   \
    int lim = min((CNT), 32);                                                   \
    _Pragma("unroll 4")                                                         \
    for (int k = 0; k < lim; k++) {                                             \
        float pk = __shfl_sync(FULL, pa, k);                                    \
        int ix = __shfl_sync(FULL, ya, k);                                      \
        agg += pk * __ldg(&g_Y[ix + lane]);                                     \
    }                                                                           \
    if ((CNT) > 32) {                                                           \
        int lim2 = (CNT) - 32;                                                  \
        for (int k = 0; k < lim2; k++) {                                        \
            float pk = __shfl_sync(FULL, pb, k);                                \
            int ix = __shfl_sync(FULL, yb, k);                                  \
            agg += pk * __ldg(&g_Y[ix + lane]);                                 \
        }                                                                       \
    }                                                                           \
}

__global__ void __launch_bounds__(BLOCK_THREADS, 1)
k_fused(const int* __restrict__ edge_src, const int* __restrict__ edge_dst,
        const int* __restrict__ edge_type, const int* __restrict__ nbr,
        const int* __restrict__ n2r, const float* __restrict__ rel_emb,
        const float* __restrict__ W1, const float* __restrict__ b1,
        float* __restrict__ out) {
    __shared__ float srel[NUM_REL * 33];    // padded, conflict-free
    __shared__ float sB[6 * 32];
    __shared__ float s_agg[16 * 32];

    const int tid  = threadIdx.x;
    const int gtid = blockIdx.x * BLOCK_THREADS + tid;

    const unsigned ep0 = ld_acq(&g_epoch);
    int* cntA = g_cnt[ep0 & 1];
    int* cntZ = g_cnt[(ep0 & 1) ^ 1];

    // ---- smem staging ----
    for (int idx = tid; idx < NUM_REL * D; idx += BLOCK_THREADS) {
        int t = idx >> 5, d = idx & 31;
        srel[t * 33 + d] = __ldg(&rel_emb[idx]);
    }
    if (tid < 6 * 32) sB[tid] = __ldg(&b1[tid]);
    __syncthreads();

    // ---- Phase A ----
    // A1: out = h0 gather (exactly one float4 per thread)
    {
        int idx = gtid;                     // NTH == E*D/4
        int e = idx >> 3;
        int t = __ldg(&edge_type[e]);
        ((float4*)out)[idx] = __ldg(&((const float4*)rel_emb)[t * 8 + (idx & 7)]);
    }
    // A2: bucket fill (packed entries)
    if (gtid < E_EDGES) {
        int s = edge_src[gtid], d0 = edge_dst[gtid], t = edge_type[gtid];
        int p = atomicAdd(&cntA[s], 1);
        if (p < CAP) g_list[s * CAP + p] = (d0 << 8) | t;
        int q = atomicAdd(&cntA[N_NODES + d0], 1);
        if (q < CAP) g_list[(N_NODES + d0) * CAP + q] = (s << 8) | t;
    }
    // A3: zero other parity for next launch
    if (gtid < 2 * N_NODES) cntZ[gtid] = 0;
    // A4: per-row metadata
    if (gtid < B_ROWS) {
        int eb = __ldg(&nbr[gtid]);
        int te = __ldg(&edge_type[eb]);
        g_row[gtid] = make_int4(__ldg(&edge_src[eb]), __ldg(&edge_dst[eb]),
                                __ldg(&n2r[gtid]) | (te << 8), eb);
    }
    // A5: Gram with leaky_relu + A6: Y = rel_emb @ W1^T (block-strided for balance)
    {
        int g = tid * GRID_BLOCKS + blockIdx.x;
        if (g < NUM_REL * NUM_REL) {
            int a = g / NUM_REL, bb = g - a * NUM_REL;
            float s = 0.f;
            #pragma unroll
            for (int d = 0; d < 32; d++) s += srel[a * 33 + d] * srel[bb * 33 + d];
            g_R[g] = s > 0.f ? s : 0.2f * s;
        }
        if (g < 6 * NUM_REL * D) {
            int d = g & 31, rest = g >> 5;           // rest = i*200 + t
            int t = rest % NUM_REL, i = rest / NUM_REL;
            const float* wrow = &W1[(i * 32 + d) * 32];   // W1[i][d][:]
            float s = 0.f;
            #pragma unroll
            for (int k = 0; k < 32; k++) s += srel[t * 33 + k] * __ldg(&wrow[k]);
            g_Y[g] = s;
        }
    }

    // ---- single grid barrier (128 blocks, all co-resident) ----
    __syncthreads();
    if (tid == 0) {
        __threadfence();
        if (atomicAdd(&g_bar_cnt, 1) == GRID_BLOCKS - 1) {
            atomicExch(&g_bar_cnt, 0);
            __threadfence();
            atomicAdd(&g_epoch, 1);
        } else {
            while (ld_acq(&g_epoch) == ep0) __nanosleep(32);
        }
    }
    __syncthreads();

    // ---- Phase B: two warps per row (even: src buckets, odd: dst buckets) ----
    const int lane = tid & 31;
    const int warp = tid >> 5;
    const int pairIdx = warp >> 1;
    const bool evenW = (warp & 1) == 0;
    const int b = blockIdx.x * 16 + pairIdx;   // < 2048 always

    int4 row = g_row[b];
    const int u = row.x, v = row.y, eb = row.w;
    const int relb = row.z & 255, tEb = (row.z >> 8) & 255;
    const float* Rrow = &g_R[relb * NUM_REL];

    const int off = evenW ? 0 : N_NODES;
    const int n1 = off + u, n2 = off + v;
    const int base1 = n1 * CAP, base2 = n2 * CAP;
    const int cnt1 = min(cntA[n1], CAP);
    const int cnt2 = min(cntA[n2], CAP);

    float agg = 0.f;
    if (evenW) {
        BUCKET(base1, cnt1, v, 4, 1, true)    // src==u: dst==v -> m4 else m1
        BUCKET(base2, cnt2, u, 5, 3, true)    // src==v: dst==u -> m5 else m3
    } else {
        BUCKET(base1, cnt1, v, 0, 0, false)   // dst==u: skip src==v, else m0
        BUCKET(base2, cnt2, u, 2, 2, false)   // dst==v: skip src==u, else m2
    }

    if (!evenW) s_agg[pairIdx * 32 + lane] = agg;
    __syncthreads();
    if (evenW) {
        float tot = agg + s_agg[pairIdx * 32 + lane];
        float hN = tot > 0.f ? tot : 0.f;
        out[(eb << 5) | lane] = srel[tEb * 33 + lane] + hN;   // distinct eb rows
    }
}

// ---------------- launcher: ONE kernel, static smem ----------------
extern "C" void kernel_launch(void* const* d_in, const int* in_sizes, int n_in,
                              void* d_out, int out_size) {
    const int*   edge_src  = (const int*)d_in[0];
    const int*   edge_dst  = (const int*)d_in[1];
    const int*   edge_type = (const int*)d_in[2];
    const int*   nbr       = (const int*)d_in[3];
    const int*   n2r       = (const int*)d_in[4];
    const float* rel_emb   = (const float*)d_in[5];
    const float* W1        = (const float*)d_in[6];
    const float* b1        = (const float*)d_in[7];
    float* out = (float*)d_out;

    k_fused<<<GRID_BLOCKS, BLOCK_THREADS>>>(
        edge_src, edge_dst, edge_type, nbr, n2r, rel_emb, W1, b1, out);
}